// round 13
// baseline (speedup 1.0000x reference)
#include <cuda_runtime.h>
#include <cuda_fp16.h>
#include <cstdint>
#include <math.h>

// ---------------- problem constants ----------------
#define N_     2
#define H_     240
#define W_     320
#define HW     76800
#define C_     128
#define HEADS_ 4
#define HD_    32
#define WS_    7
#define DEPTH_ 4
#define HID_   512
#define NWH_   35
#define NWW_   46
#define NWIN_  (N_*NWH_*NWW_) // 3220
#define WT_    49
#define TOKW_  (NWIN_*WT_)    // 157780
#define NQ_    128
#define DOUT_  256

// weight scratch offsets (halves)
#define WH_CONV 0
#define WH_QKV  16384
#define WH_PROJ (16384+196608)
#define WH_FC1  (16384+196608+65536)
#define WH_FC2  (16384+196608+65536+262144)
#define WH_TOT  (16384+196608+65536+262144+262144)

// ---------------- scratch (device globals) ----------------
__device__ __half g_xth   [(size_t)N_*HW*C_];
__device__ __half g_tok0h [(size_t)N_*HW*C_];
__device__ float  g_tokens[(size_t)N_*HW*C_];
__device__ __half g_hh    [(size_t)TOKW_*C_];
__device__ __half g_qkvh  [(size_t)TOKW_*3*C_];
__device__ __half g_attnoh[(size_t)TOKW_*C_];
__device__ __half g_mlp1h [(size_t)N_*HW*HID_];
__device__ __half g_wh    [WH_TOT];
__device__ __half g_qh    [N_*NQ_*C_];
__device__ float  g_head  [N_*C_];

// ---------------- helpers ----------------
__device__ __forceinline__ uint32_t smem_u32(const void* p) {
    uint32_t a;
    asm("{ .reg .u64 t; cvta.to.shared.u64 t, %1; cvt.u32.u64 %0, t; }" : "=r"(a) : "l"(p));
    return a;
}
__device__ __forceinline__ float warp_sum(float v) {
    #pragma unroll
    for (int o = 16; o; o >>= 1) v += __shfl_xor_sync(0xffffffffu, v, o);
    return v;
}
__device__ __forceinline__ float gelu_exact(float x) {
    return 0.5f * x * (1.0f + erff(x * 0.70710678118654752f));
}
__device__ __forceinline__ void ldsm_x4(uint32_t& r0, uint32_t& r1, uint32_t& r2, uint32_t& r3,
                                        uint32_t addr) {
    asm volatile("ldmatrix.sync.aligned.m8n8.x4.shared.b16 {%0,%1,%2,%3}, [%4];"
                 : "=r"(r0), "=r"(r1), "=r"(r2), "=r"(r3) : "r"(addr));
}
__device__ __forceinline__ void ldsm_x4t(uint32_t& r0, uint32_t& r1, uint32_t& r2, uint32_t& r3,
                                         uint32_t addr) {
    asm volatile("ldmatrix.sync.aligned.m8n8.x4.trans.shared.b16 {%0,%1,%2,%3}, [%4];"
                 : "=r"(r0), "=r"(r1), "=r"(r2), "=r"(r3) : "r"(addr));
}
__device__ __forceinline__ void mma16816(float* c, const uint32_t* a, const uint32_t* b) {
    asm volatile(
        "mma.sync.aligned.m16n8k16.row.col.f32.f16.f16.f32 "
        "{%0,%1,%2,%3}, {%4,%5,%6,%7}, {%8,%9}, {%0,%1,%2,%3};"
        : "+f"(c[0]), "+f"(c[1]), "+f"(c[2]), "+f"(c[3])
        : "r"(a[0]), "r"(a[1]), "r"(a[2]), "r"(a[3]), "r"(b[0]), "r"(b[1]));
}
#define CP16(dst, src) \
    asm volatile("cp.async.cg.shared.global [%0], [%1], 16;" :: "r"(dst), "l"(src))
#define CP_COMMIT() asm volatile("cp.async.commit_group;" ::: "memory")
#define CP_WAIT0()  asm volatile("cp.async.wait_group 0;" ::: "memory")
#define CP_WAIT1()  asm volatile("cp.async.wait_group 1;" ::: "memory")

// ================= fp16 mma.sync GEMM, K-chunk 64, compile-time K, 2/3-stage =================
// EPI: 0 fp32 store, 1 half store, 2 gelu+half store, 3 scatter-add into tokens,
//      4 fp32 accumulate, 5 dual: fp32 store + half store
// BZ: 1 = batch over blockIdx.z (maps)
// MINB: min blocks/SM target (3 => <=85 regs)
#define KR_ 72                   // smem row stride in halves (144B), conflict-free
#define STG_ (128*KR_*2)         // bytes per stage per matrix = 18432
#define GEMM_SMEM2 (4*STG_)      // 73728
#define GEMM_SMEM3 (6*STG_)      // 110592

template <int EPI, int K, int STAGES = 2, int BZ = 0, int MINB = 2>
__global__ __launch_bounds__(256, MINB)
void gemm_mma(const __half* __restrict__ A, const __half* __restrict__ B,
              const float* __restrict__ bias, float* __restrict__ Cf,
              __half* __restrict__ Ch, int M, int N) {
    extern __shared__ __align__(16) char smem[];
    const uint32_t sS = smem_u32(smem);

    if (BZ) {
        A  += (size_t)blockIdx.z * NQ_ * C_;
        B  += (size_t)blockIdx.z * HW * C_;
        Cf += (size_t)blockIdx.z * NQ_ * HW;
    }

    const int tid = threadIdx.x;
    const int wid = tid >> 5, lane = tid & 31;
    const int tileN = blockIdx.x * 128, tileM = blockIdx.y * 128;
    const int wm = (wid >> 2) * 64, wn = (wid & 3) * 32;
    const int rr = lane & 7, gg = lane >> 3;

    float acc[4][4][4];
    #pragma unroll
    for (int i = 0; i < 4; i++)
        #pragma unroll
        for (int j = 0; j < 4; j++)
            #pragma unroll
            for (int k = 0; k < 4; k++) acc[i][j][k] = 0.f;

    constexpr int KC = K >> 6;

    auto issue = [&](int kc, int stg) {
        int kb = kc * 64;
        #pragma unroll
        for (int q = 0; q < 4; q++) {
            int slot = tid + q * 256;
            int r = slot >> 3, c8 = (slot & 7) * 8;
            uint32_t da = sS + stg * STG_ + (uint32_t)(r * KR_ + c8) * 2;
            if (tileM + r < M) CP16(da, A + (size_t)(tileM + r) * K + kb + c8);
            uint32_t db = sS + STAGES * STG_ + stg * STG_ + (uint32_t)(r * KR_ + c8) * 2;
            if (tileN + r < N) CP16(db, B + (size_t)(tileN + r) * K + kb + c8);
        }
    };

    issue(0, 0); CP_COMMIT();
    if (STAGES == 3) {
        if (KC > 1) issue(1, 1);
        CP_COMMIT();
    }

    #pragma unroll
    for (int kc = 0; kc < KC; kc++) {
        if (STAGES == 3) { CP_WAIT1(); } else { CP_WAIT0(); }
        __syncthreads();
        int pc = kc + (STAGES - 1);
        if (pc < KC) issue(pc, pc % STAGES);
        CP_COMMIT();

        const int stg = kc % STAGES;
        const uint32_t aBase = sS + stg * STG_;
        const uint32_t bBase = sS + STAGES * STG_ + stg * STG_;
        #pragma unroll
        for (int ks = 0; ks < 4; ks++) {
            uint32_t a[4][4];
            #pragma unroll
            for (int mi = 0; mi < 4; mi++) {
                int row = wm + mi * 16 + rr + ((gg & 1) << 3);
                int col = ks * 16 + ((gg >> 1) << 3);
                ldsm_x4(a[mi][0], a[mi][1], a[mi][2], a[mi][3],
                        aBase + (uint32_t)(row * KR_ + col) * 2);
            }
            uint32_t b[2][4];
            #pragma unroll
            for (int p = 0; p < 2; p++) {
                int row = wn + p * 16 + rr + ((gg & 1) << 3);
                int col = ks * 16 + ((gg >> 1) << 3);
                ldsm_x4(b[p][0], b[p][1], b[p][2], b[p][3],
                        bBase + (uint32_t)(row * KR_ + col) * 2);
            }
            #pragma unroll
            for (int mi = 0; mi < 4; mi++) {
                #pragma unroll
                for (int nj = 0; nj < 4; nj++) {
                    int p = nj >> 1;
                    uint32_t bb[2];
                    if (nj & 1) { bb[0] = b[p][1]; bb[1] = b[p][3]; }
                    else        { bb[0] = b[p][0]; bb[1] = b[p][2]; }
                    mma16816(acc[mi][nj], a[mi], bb);
                }
            }
        }
    }

    const int er = lane >> 2, ec = (lane & 3) * 2;
    #pragma unroll
    for (int mi = 0; mi < 4; mi++) {
        #pragma unroll
        for (int half = 0; half < 2; half++) {
            int gm = tileM + wm + mi * 16 + er + half * 8;
            if (gm >= M) continue;
            #pragma unroll
            for (int nj = 0; nj < 4; nj++) {
                int gn = tileN + wn + nj * 8 + ec;
                float vx = acc[mi][nj][half * 2 + 0];
                float vy = acc[mi][nj][half * 2 + 1];
                if (bias) { vx += bias[gn]; vy += bias[gn + 1]; }
                if (EPI == 2) { vx = gelu_exact(vx); vy = gelu_exact(vy); }
                if (EPI == 1 || EPI == 2) {
                    *(__half2*)(Ch + (size_t)gm * N + gn) = __floats2half2_rn(vx, vy);
                } else if (EPI == 3) {
                    int w = gm / WT_, i = gm - w * WT_;
                    int n = w / (NWH_ * NWW_); int rem = w - n * (NWH_ * NWW_);
                    int wh = rem / NWW_, ww = rem - wh * NWW_;
                    int hp = wh * WS_ + i / WS_;
                    int wp = ww * WS_ + i - (i / WS_) * WS_;
                    if (hp < H_ && wp < W_) {
                        size_t o = ((size_t)n * HW + hp * W_ + wp) * C_ + gn;
                        float2 old = *(float2*)(Cf + o);
                        *(float2*)(Cf + o) = make_float2(old.x + vx, old.y + vy);
                    }
                } else if (EPI == 4) {
                    size_t o = (size_t)gm * N + gn;
                    float2 old = *(float2*)(Cf + o);
                    *(float2*)(Cf + o) = make_float2(old.x + vx, old.y + vy);
                } else {
                    size_t o = (size_t)gm * N + gn;
                    *(float2*)(Cf + o) = make_float2(vx, vy);
                    if (EPI == 5)
                        *(__half2*)(Ch + o) = __floats2half2_rn(vx, vy);
                }
            }
        }
    }
}

// ---------------- all weights fp32 -> fp16, one kernel ----------------
__global__ void cvt_weights(const float* __restrict__ cw, const float* __restrict__ qw,
                            const float* __restrict__ pw, const float* __restrict__ f1,
                            const float* __restrict__ f2, __half* __restrict__ wh) {
    int i = blockIdx.x * blockDim.x + threadIdx.x;
    const float* s; int off;
    if (i < WH_QKV)      { s = cw; off = 0; }
    else if (i < WH_PROJ){ s = qw; off = WH_QKV; }
    else if (i < WH_FC1) { s = pw; off = WH_PROJ; }
    else if (i < WH_FC2) { s = f1; off = WH_FC1; }
    else if (i < WH_TOT) { s = f2; off = WH_FC2; }
    else return;
    wh[i] = __float2half(s[i - off]);
}

// ---------------- transpose (n,c,p) -> (n,p,c), fp32 -> half ----------------
__global__ void transpose_ncp(const float* __restrict__ in, __half* __restrict__ out) {
    __shared__ float tile[32][33];
    int n = blockIdx.z;
    int p0 = blockIdx.x * 32, c0 = blockIdx.y * 32;
    int x = threadIdx.x, y = threadIdx.y;
    const float* src = in + (size_t)n * C_ * HW;
    #pragma unroll
    for (int yy = y; yy < 32; yy += 8)
        tile[yy][x] = src[(size_t)(c0 + yy) * HW + p0 + x];
    __syncthreads();
    __half* dst = out + (size_t)n * HW * C_;
    #pragma unroll
    for (int yy = y; yy < 32; yy += 8)
        dst[(size_t)(p0 + yy) * C_ + c0 + x] = __float2half(tile[x][yy]);
}

// ---------------- LN over C=128 into padded window layout, half out (vectorized) ----------------
__global__ void ln_window(const float* __restrict__ tokens,
                          const float* __restrict__ g, const float* __restrict__ b,
                          __half* __restrict__ out) {
    int warp = (blockIdx.x * blockDim.x + threadIdx.x) >> 5;
    int lane = threadIdx.x & 31;
    if (warp >= TOKW_) return;
    int w = warp / WT_, i = warp % WT_;
    int n = w / (NWH_ * NWW_); int rem = w % (NWH_ * NWW_);
    int wh = rem / NWW_, ww = rem % NWW_;
    int hp = wh * WS_ + i / WS_;
    int wp = ww * WS_ + i % WS_;
    __half* orow = out + (size_t)warp * C_;
    if (hp < H_ && wp < W_) {
        const float* irow = tokens + ((size_t)n * HW + hp * W_ + wp) * C_;
        float4 v = *(const float4*)(irow + 4 * lane);
        float mu = warp_sum(v.x + v.y + v.z + v.w) * (1.f / C_);
        float d0 = v.x - mu, d1 = v.y - mu, d2 = v.z - mu, d3 = v.w - mu;
        float var = warp_sum(d0 * d0 + d1 * d1 + d2 * d2 + d3 * d3) * (1.f / C_);
        float rstd = rsqrtf(var + 1e-5f);
        float4 gw = *(const float4*)(g + 4 * lane);
        float4 bw = *(const float4*)(b + 4 * lane);
        __half2 h0 = __floats2half2_rn(d0 * rstd * gw.x + bw.x, d1 * rstd * gw.y + bw.y);
        __half2 h1 = __floats2half2_rn(d2 * rstd * gw.z + bw.z, d3 * rstd * gw.w + bw.w);
        uint2 pk;
        pk.x = *(uint32_t*)&h0; pk.y = *(uint32_t*)&h1;
        *(uint2*)(orow + 4 * lane) = pk;
    } else {
        *(uint2*)(orow + 4 * lane) = make_uint2(0u, 0u);
    }
}

// ---------------- plain LN over rows, half out (vectorized) ----------------
__global__ void ln_rows(const float* __restrict__ in,
                        const float* __restrict__ g, const float* __restrict__ b,
                        __half* __restrict__ out, int rows) {
    int warp = (blockIdx.x * blockDim.x + threadIdx.x) >> 5;
    int lane = threadIdx.x & 31;
    if (warp >= rows) return;
    const float* irow = in + (size_t)warp * C_;
    float4 v = *(const float4*)(irow + 4 * lane);
    float mu = warp_sum(v.x + v.y + v.z + v.w) * (1.f / C_);
    float d0 = v.x - mu, d1 = v.y - mu, d2 = v.z - mu, d3 = v.w - mu;
    float var = warp_sum(d0 * d0 + d1 * d1 + d2 * d2 + d3 * d3) * (1.f / C_);
    float rstd = rsqrtf(var + 1e-5f);
    float4 gw = *(const float4*)(g + 4 * lane);
    float4 bw = *(const float4*)(b + 4 * lane);
    __half2 h0 = __floats2half2_rn(d0 * rstd * gw.x + bw.x, d1 * rstd * gw.y + bw.y);
    __half2 h1 = __floats2half2_rn(d2 * rstd * gw.z + bw.z, d3 * rstd * gw.w + bw.w);
    __half* orow = out + (size_t)warp * C_;
    uint2 pk;
    pk.x = *(uint32_t*)&h0; pk.y = *(uint32_t*)&h1;
    *(uint2*)(orow + 4 * lane) = pk;
}

// ================= attention: tensor cores, one warp per head, P overlays Q/K =================
#define AP_QKV(t, h) ((h)*7680 + (t)*2560)
#define AP_P(h)      ((h)*7680)
#define ATTN_SMEM    (30720 * 2)   // 61440 bytes

__global__ __launch_bounds__(128)
void attn_win(const __half* __restrict__ qkv, __half* __restrict__ out) {
    extern __shared__ __align__(16) __half ash[];
    const int w = blockIdx.x;
    const int tid = threadIdx.x;
    const int wid = tid >> 5, lane = tid & 31;
    const int rr = lane & 7, gg = lane >> 3;
    const int q2 = (lane & 3) * 2;
    const uint32_t sb = smem_u32(ash);

    const __half* src = qkv + (size_t)w * WT_ * 384;
    for (int idx = tid; idx < WT_ * 48; idx += 128) {
        int r = idx / 48, u = idx % 48;
        int t = u >> 4, h = (u >> 2) & 3, seg = u & 3;
        uint32_t dst = sb + (uint32_t)((AP_QKV(t, h) + r * 40 + seg * 8)) * 2;
        CP16(dst, src + (size_t)r * 384 + u * 8);
    }
    CP_COMMIT();
    uint4 z = make_uint4(0u, 0u, 0u, 0u);
    for (int idx = tid; idx < 900; idx += 128) {
        int plane = idx / 75, rem = idx % 75;
        int r = 49 + rem / 5, seg = rem % 5;
        *(uint4*)((char*)ash + (size_t)(plane * 2560 + r * 40 + seg * 8) * 2) = z;
    }
    CP_WAIT0();
    __syncthreads();

    const int h = wid;
    const uint32_t sQ = sb + (uint32_t)AP_QKV(0, h) * 2;
    const uint32_t sK = sb + (uint32_t)AP_QKV(1, h) * 2;
    const uint32_t sV = sb + (uint32_t)AP_QKV(2, h) * 2;
    const uint32_t sP = sb + (uint32_t)AP_P(h) * 2;
    __half* Pp = ash + AP_P(h);

    float s[4][7][4];
    #pragma unroll
    for (int i = 0; i < 4; i++)
        #pragma unroll
        for (int j = 0; j < 7; j++)
            #pragma unroll
            for (int k = 0; k < 4; k++) s[i][j][k] = 0.f;

    #pragma unroll
    for (int ks = 0; ks < 2; ks++) {
        uint32_t a[4][4];
        #pragma unroll
        for (int mi = 0; mi < 4; mi++)
            ldsm_x4(a[mi][0], a[mi][1], a[mi][2], a[mi][3],
                    sQ + (uint32_t)((mi * 16 + rr + ((gg & 1) << 3)) * 40
                                    + ks * 16 + ((gg >> 1) << 3)) * 2);
        uint32_t b[4][4];
        #pragma unroll
        for (int p = 0; p < 4; p++)
            ldsm_x4(b[p][0], b[p][1], b[p][2], b[p][3],
                    sK + (uint32_t)((p * 16 + rr + ((gg & 1) << 3)) * 40
                                    + ks * 16 + ((gg >> 1) << 3)) * 2);
        #pragma unroll
        for (int mi = 0; mi < 4; mi++)
            #pragma unroll
            for (int nj = 0; nj < 7; nj++) {
                int pg = nj >> 1;
                uint32_t bb[2];
                if (nj & 1) { bb[0] = b[pg][1]; bb[1] = b[pg][3]; }
                else        { bb[0] = b[pg][0]; bb[1] = b[pg][2]; }
                mma16816(s[mi][nj], a[mi], bb);
            }
    }
    __syncwarp();

    const float scale = 0.17677669529663687f;
    #pragma unroll
    for (int mi = 0; mi < 4; mi++) {
        #pragma unroll
        for (int hf = 0; hf < 2; hf++) {
            float mx = -1e30f;
            #pragma unroll
            for (int nj = 0; nj < 7; nj++) {
                int c0 = 8 * nj + q2;
                float v0 = s[mi][nj][hf * 2 + 0];
                float v1 = s[mi][nj][hf * 2 + 1];
                if (c0 < WT_) mx = fmaxf(mx, v0);
                if (c0 + 1 < WT_) mx = fmaxf(mx, v1);
            }
            mx = fmaxf(mx, __shfl_xor_sync(0xffffffffu, mx, 1));
            mx = fmaxf(mx, __shfl_xor_sync(0xffffffffu, mx, 2));
            float p0[7], p1[7], sum = 0.f;
            #pragma unroll
            for (int nj = 0; nj < 7; nj++) {
                int c0 = 8 * nj + q2;
                float v0 = s[mi][nj][hf * 2 + 0];
                float v1 = s[mi][nj][hf * 2 + 1];
                p0[nj] = (c0 < WT_)     ? __expf((v0 - mx) * scale) : 0.f;
                p1[nj] = (c0 + 1 < WT_) ? __expf((v1 - mx) * scale) : 0.f;
                sum += p0[nj] + p1[nj];
            }
            sum += __shfl_xor_sync(0xffffffffu, sum, 1);
            sum += __shfl_xor_sync(0xffffffffu, sum, 2);
            float inv = 1.f / sum;
            int row = mi * 16 + (lane >> 2) + hf * 8;
            #pragma unroll
            for (int nj = 0; nj < 7; nj++)
                *(__half2*)(Pp + row * 72 + 8 * nj + q2) =
                    __floats2half2_rn(p0[nj] * inv, p1[nj] * inv);
        }
    }
    for (int r = lane; r < 64; r += 32)
        *(uint4*)(Pp + r * 72 + 56) = make_uint4(0u, 0u, 0u, 0u);
    __syncwarp();

    float o[4][4][4];
    #pragma unroll
    for (int i = 0; i < 4; i++)
        #pragma unroll
        for (int j = 0; j < 4; j++)
            #pragma unroll
            for (int k = 0; k < 4; k++) o[i][j][k] = 0.f;

    #pragma unroll
    for (int ks = 0; ks < 4; ks++) {
        uint32_t a[4][4];
        #pragma unroll
        for (int mi = 0; mi < 4; mi++)
            ldsm_x4(a[mi][0], a[mi][1], a[mi][2], a[mi][3],
                    sP + (uint32_t)((mi * 16 + rr + ((gg & 1) << 3)) * 72
                                    + ks * 16 + ((gg >> 1) << 3)) * 2);
        uint32_t b[2][4];
        #pragma unroll
        for (int g = 0; g < 2; g++) {
            int row = ks * 16 + rr + ((gg >> 1) << 3);
            int col = g * 16 + ((gg & 1) << 3);
            ldsm_x4t(b[g][0], b[g][1], b[g][2], b[g][3],
                     sV + (uint32_t)(row * 40 + col) * 2);
        }
        #pragma unroll
        for (int mi = 0; mi < 4; mi++)
            #pragma unroll
            for (int nd = 0; nd < 4; nd++) {
                int g = nd >> 1;
                uint32_t bb[2];
                if (nd & 1) { bb[0] = b[g][1]; bb[1] = b[g][3]; }
                else        { bb[0] = b[g][0]; bb[1] = b[g][2]; }
                mma16816(o[mi][nd], a[mi], bb);
            }
    }

    #pragma unroll
    for (int mi = 0; mi < 4; mi++) {
        #pragma unroll
        for (int hf = 0; hf < 2; hf++) {
            int row = mi * 16 + (lane >> 2) + hf * 8;
            if (row < WT_) {
                #pragma unroll
                for (int nd = 0; nd < 4; nd++)
                    *(__half2*)(out + ((size_t)(w * WT_ + row)) * C_ + h * HD_ + 8 * nd + q2) =
                        __floats2half2_rn(o[mi][nd][hf * 2], o[mi][nd][hf * 2 + 1]);
            }
        }
    }
}

// ---------------- head mean reduce + tiny MLP ----------------
__global__ void zero_head() { if (threadIdx.x < N_ * C_) g_head[threadIdx.x] = 0.f; }

__global__ void head_reduce(const float* __restrict__ tokens) {
    int n = blockIdx.x / (HW / 128);
    int pb = (blockIdx.x % (HW / 128)) * 128;
    int c = threadIdx.x;
    float s = 0.f;
    for (int i = 0; i < 128; i++) s += tokens[((size_t)n * HW + pb + i) * C_ + c];
    atomicAdd(&g_head[n * C_ + c], s);
}

__global__ void head_mlp(const float* __restrict__ r1w, const float* __restrict__ r1b,
                         const float* __restrict__ r2w, const float* __restrict__ r2b,
                         const float* __restrict__ r3w, const float* __restrict__ r3b,
                         float* __restrict__ out) {
    __shared__ float hh[N_ * C_];
    __shared__ float y1[N_ * 256];
    __shared__ float y2[N_ * 256];
    __shared__ float y3[N_ * DOUT_];
    __shared__ float ssum[N_];
    int tid = threadIdx.x;
    if (tid < N_ * C_) hh[tid] = g_head[tid] * (1.f / HW);
    __syncthreads();
    for (int o = tid; o < N_ * 256; o += 256) {
        int n = o >> 8, j = o & 255;
        float s = r1b[j];
        for (int c = 0; c < C_; c++) s = fmaf(hh[n * C_ + c], r1w[j * C_ + c], s);
        y1[o] = s > 0.f ? s : 0.01f * s;
    }
    __syncthreads();
    for (int o = tid; o < N_ * 256; o += 256) {
        int n = o >> 8, j = o & 255;
        float s = r2b[j];
        for (int c = 0; c < 256; c++) s = fmaf(y1[n * 256 + c], r2w[j * 256 + c], s);
        y2[o] = s > 0.f ? s : 0.01f * s;
    }
    __syncthreads();
    for (int o = tid; o < N_ * DOUT_; o += 256) {
        int n = o >> 8, j = o & 255;
        float s = r3b[j];
        for (int c = 0; c < 256; c++) s = fmaf(y2[n * 256 + c], r3w[j * 256 + c], s);
        y3[o] = fmaxf(s, 0.f) + 0.1f;
    }
    __syncthreads();
    if (tid < N_) {
        float s = 0.f;
        for (int j = 0; j < DOUT_; j++) s += y3[tid * DOUT_ + j];
        ssum[tid] = s;
    }
    __syncthreads();
    for (int o = tid; o < N_ * DOUT_; o += 256) {
        int n = o >> 8;
        out[o] = y3[o] / ssum[n];
    }
}

// ---------------- queries fp32 -> half ----------------
__global__ void cvt_queries(const float* __restrict__ tokens, __half* __restrict__ qh) {
    int i = blockIdx.x * blockDim.x + threadIdx.x;
    if (i < N_ * NQ_ * C_) {
        int n = i / (NQ_ * C_);
        int r = i - n * (NQ_ * C_);
        qh[i] = __float2half(tokens[(size_t)n * HW * C_ + r]);
    }
}

// ---------------- host launch ----------------
static void* symaddr(const void* sym) {
    void* p = nullptr;
    cudaGetSymbolAddress(&p, sym);
    return p;
}

extern "C" void kernel_launch(void* const* d_in, const int* in_sizes, int n_in,
                              void* d_out, int out_size) {
    const float* x      = (const float*)d_in[0];
    const float* conv_w = (const float*)d_in[1];
    const float* conv_b = (const float*)d_in[2];
    const float* n1_g   = (const float*)d_in[3];
    const float* n1_b   = (const float*)d_in[4];
    const float* qkv_w  = (const float*)d_in[5];
    const float* qkv_b  = (const float*)d_in[6];
    const float* proj_w = (const float*)d_in[7];
    const float* proj_b = (const float*)d_in[8];
    const float* n2_g   = (const float*)d_in[9];
    const float* n2_b   = (const float*)d_in[10];
    const float* fc1_w  = (const float*)d_in[11];
    const float* fc1_b  = (const float*)d_in[12];
    const float* fc2_w  = (const float*)d_in[13];
    const float* fc2_b  = (const float*)d_in[14];
    const float* r1_w   = (const float*)d_in[15];
    const float* r1_b   = (const float*)d_in[16];
    const float* r2_w   = (const float*)d_in[17];
    const float* r2_b   = (const float*)d_in[18];
    const float* r3_w   = (const float*)d_in[19];
    const float* r3_b   = (const float*)d_in[20];
    float* out = (float*)d_out;

    __half* xth    = (__half*)symaddr(g_xth);
    __half* tok0h  = (__half*)symaddr(g_tok0h);
    float*  tokens = (float*)symaddr(g_tokens);
    __half* hh     = (__half*)symaddr(g_hh);
    __half* qkvh   = (__half*)symaddr(g_qkvh);
    __half* attnoh = (__half*)symaddr(g_attnoh);
    __half* mlp1h  = (__half*)symaddr(g_mlp1h);
    __half* wh     = (__half*)symaddr(g_wh);
    __half* qh     = (__half*)symaddr(g_qh);

    cudaFuncSetAttribute((const void*)gemm_mma<0,128,2,1,3>, cudaFuncAttributeMaxDynamicSharedMemorySize, GEMM_SMEM2);
    cudaFuncSetAttribute((const void*)gemm_mma<1,128,2,0,3>, cudaFuncAttributeMaxDynamicSharedMemorySize, GEMM_SMEM2);
    cudaFuncSetAttribute((const void*)gemm_mma<2,128,2,0,3>, cudaFuncAttributeMaxDynamicSharedMemorySize, GEMM_SMEM2);
    cudaFuncSetAttribute((const void*)gemm_mma<3,128,2,0,3>, cudaFuncAttributeMaxDynamicSharedMemorySize, GEMM_SMEM2);
    cudaFuncSetAttribute((const void*)gemm_mma<4,512,3,0,2>, cudaFuncAttributeMaxDynamicSharedMemorySize, GEMM_SMEM3);
    cudaFuncSetAttribute((const void*)gemm_mma<5,128,2,0,3>, cudaFuncAttributeMaxDynamicSharedMemorySize, GEMM_SMEM2);
    cudaFuncSetAttribute((const void*)attn_win, cudaFuncAttributeMaxDynamicSharedMemorySize, ATTN_SMEM);

    cvt_weights<<<(WH_TOT + 255) / 256, 256>>>(conv_w, qkv_w, proj_w, fc1_w, fc2_w, wh);

    transpose_ncp<<<dim3(HW / 32, C_ / 32, N_), dim3(32, 8)>>>(x, xth);

    gemm_mma<5,128,2,0,3><<<dim3(1, (N_ * HW) / 128), 256, GEMM_SMEM2>>>(
        xth, wh + WH_CONV, conv_b, tokens, tok0h, N_ * HW, C_);

    const int mTiles_w = (TOKW_ + 127) / 128;
    const int lnw_blocks = (TOKW_ + 7) / 8;
    const int lnr_blocks = (N_ * HW + 7) / 8;

    for (int d = 0; d < DEPTH_; d++) {
        ln_window<<<lnw_blocks, 256>>>(tokens, n1_g + d * C_, n1_b + d * C_, hh);
        gemm_mma<1,128,2,0,3><<<dim3(3, mTiles_w), 256, GEMM_SMEM2>>>(
            hh, wh + WH_QKV + (size_t)d * 3 * C_ * C_, qkv_b + d * 3 * C_,
            nullptr, qkvh, TOKW_, 3 * C_);
        attn_win<<<NWIN_, 128, ATTN_SMEM>>>(qkvh, attnoh);
        gemm_mma<3,128,2,0,3><<<dim3(1, mTiles_w), 256, GEMM_SMEM2>>>(
            attnoh, wh + WH_PROJ + (size_t)d * C_ * C_, proj_b + d * C_,
            tokens, nullptr, TOKW_, C_);
        ln_rows<<<lnr_blocks, 256>>>(tokens, n2_g + d * C_, n2_b + d * C_, hh, N_ * HW);
        gemm_mma<2,128,2,0,3><<<dim3(HID_ / 128, (N_ * HW) / 128), 256, GEMM_SMEM2>>>(
            hh, wh + WH_FC1 + (size_t)d * HID_ * C_, fc1_b + d * HID_,
            nullptr, mlp1h, N_ * HW, HID_);
        gemm_mma<4,512,3,0,2><<<dim3(1, (N_ * HW) / 128), 256, GEMM_SMEM3>>>(
            mlp1h, wh + WH_FC2 + (size_t)d * C_ * HID_, fc2_b + d * C_,
            tokens, nullptr, N_ * HW, C_);
    }

    zero_head<<<1, 256>>>();
    head_reduce<<<N_ * (HW / 128), 128>>>(tokens);
    head_mlp<<<1, 256>>>(r1_w, r1_b, r2_w, r2_b, r3_w, r3_b, out);

    cvt_queries<<<(N_ * NQ_ * C_ + 255) / 256, 256>>>(tokens, qh);
    gemm_mma<0,128,2,1,3><<<dim3(HW / 128, 1, N_), 256, GEMM_SMEM2>>>(
        qh, tok0h, nullptr, out + 512, nullptr, NQ_, HW);
}

// round 15
// speedup vs baseline: 1.1218x; 1.1218x over previous
#include <cuda_runtime.h>
#include <cuda_fp16.h>
#include <cstdint>
#include <math.h>

// ---------------- problem constants ----------------
#define N_     2
#define H_     240
#define W_     320
#define HW     76800
#define C_     128
#define HEADS_ 4
#define HD_    32
#define WS_    7
#define DEPTH_ 4
#define HID_   512
#define NWH_   35
#define NWW_   46
#define NWIN_  (N_*NWH_*NWW_) // 3220
#define WT_    49
#define TOKW_  (NWIN_*WT_)    // 157780
#define NQ_    128
#define DOUT_  256

// weight scratch offsets (halves)
#define WH_CONV 0
#define WH_QKV  16384
#define WH_PROJ (16384+196608)
#define WH_FC1  (16384+196608+65536)
#define WH_FC2  (16384+196608+65536+262144)
#define WH_TOT  (16384+196608+65536+262144+262144)

// ---------------- scratch (device globals) ----------------
__device__ __half g_xth   [(size_t)N_*HW*C_];
__device__ __half g_tok0h [(size_t)N_*HW*C_];
__device__ float  g_tokens[(size_t)N_*HW*C_];
__device__ __half g_hh    [(size_t)TOKW_*C_];
__device__ __half g_qkvh  [(size_t)TOKW_*3*C_];
__device__ __half g_attnoh[(size_t)TOKW_*C_];
__device__ __half g_mlp1h [(size_t)N_*HW*HID_];
__device__ __half g_wh    [WH_TOT];
__device__ __half g_qh    [N_*NQ_*C_];
__device__ float  g_head  [N_*C_];

// ---------------- helpers ----------------
__device__ __forceinline__ uint32_t smem_u32(const void* p) {
    uint32_t a;
    asm("{ .reg .u64 t; cvta.to.shared.u64 t, %1; cvt.u32.u64 %0, t; }" : "=r"(a) : "l"(p));
    return a;
}
__device__ __forceinline__ float warp_sum(float v) {
    #pragma unroll
    for (int o = 16; o; o >>= 1) v += __shfl_xor_sync(0xffffffffu, v, o);
    return v;
}
__device__ __forceinline__ float gelu_exact(float x) {
    return 0.5f * x * (1.0f + erff(x * 0.70710678118654752f));
}
__device__ __forceinline__ void ldsm_x4(uint32_t& r0, uint32_t& r1, uint32_t& r2, uint32_t& r3,
                                        uint32_t addr) {
    asm volatile("ldmatrix.sync.aligned.m8n8.x4.shared.b16 {%0,%1,%2,%3}, [%4];"
                 : "=r"(r0), "=r"(r1), "=r"(r2), "=r"(r3) : "r"(addr));
}
__device__ __forceinline__ void ldsm_x4t(uint32_t& r0, uint32_t& r1, uint32_t& r2, uint32_t& r3,
                                         uint32_t addr) {
    asm volatile("ldmatrix.sync.aligned.m8n8.x4.trans.shared.b16 {%0,%1,%2,%3}, [%4];"
                 : "=r"(r0), "=r"(r1), "=r"(r2), "=r"(r3) : "r"(addr));
}
__device__ __forceinline__ void mma16816(float* c, const uint32_t* a, const uint32_t* b) {
    asm volatile(
        "mma.sync.aligned.m16n8k16.row.col.f32.f16.f16.f32 "
        "{%0,%1,%2,%3}, {%4,%5,%6,%7}, {%8,%9}, {%0,%1,%2,%3};"
        : "+f"(c[0]), "+f"(c[1]), "+f"(c[2]), "+f"(c[3])
        : "r"(a[0]), "r"(a[1]), "r"(a[2]), "r"(a[3]), "r"(b[0]), "r"(b[1]));
}
#define CP16(dst, src) \
    asm volatile("cp.async.cg.shared.global [%0], [%1], 16;" :: "r"(dst), "l"(src))
#define CP_COMMIT() asm volatile("cp.async.commit_group;" ::: "memory")
#define CP_WAIT0()  asm volatile("cp.async.wait_group 0;" ::: "memory")
#define CP_WAIT1()  asm volatile("cp.async.wait_group 1;" ::: "memory")

// ================= fp16 mma.sync GEMM =================
// K=128 path: single full-K buffer (stride 136 halves = 272B rows, conflict-free),
//             16 front-batched cp.asyncs/thread, one wait + one sync, 8 k-steps.
// K=512 path: 3-stage cp.async pipeline, K-chunk 64 (stride 72).
// EPI: 0 fp32 store, 1 half store, 2 gelu+half store, 3 scatter-add into tokens,
//      4 fp32 accumulate, 5 dual: fp32 store + half store
// BZ: 1 = batch over blockIdx.z (maps)
#define KR_ 72
#define STG_ (128*KR_*2)          // 18432
#define GEMM_SMEM3 (6*STG_)       // 110592 (K=512, 3-stage)
#define FR_ 136                   // full-K row stride in halves (272B)
#define FBUF_ (128*FR_*2)         // 34816 per matrix
#define GEMM_SMEM1 (2*FBUF_)      // 69632 (K=128 single buffer)

template <int EPI, int K, int STAGES = 1, int BZ = 0>
__global__ __launch_bounds__(256)
void gemm_mma(const __half* __restrict__ A, const __half* __restrict__ B,
              const float* __restrict__ bias, float* __restrict__ Cf,
              __half* __restrict__ Ch, int M, int N) {
    extern __shared__ __align__(16) char smem[];
    const uint32_t sS = smem_u32(smem);

    if (BZ) {
        A  += (size_t)blockIdx.z * NQ_ * C_;
        B  += (size_t)blockIdx.z * HW * C_;
        Cf += (size_t)blockIdx.z * NQ_ * HW;
    }

    const int tid = threadIdx.x;
    const int wid = tid >> 5, lane = tid & 31;
    const int tileN = blockIdx.x * 128, tileM = blockIdx.y * 128;
    const int wm = (wid >> 2) * 64, wn = (wid & 3) * 32;
    const int rr = lane & 7, gg = lane >> 3;

    float acc[4][4][4];
    #pragma unroll
    for (int i = 0; i < 4; i++)
        #pragma unroll
        for (int j = 0; j < 4; j++)
            #pragma unroll
            for (int k = 0; k < 4; k++) acc[i][j][k] = 0.f;

    if (STAGES == 1) {
        // ---- K=128: one shot, full coverage: 4096 CP16 = 16/thread ----
        #pragma unroll
        for (int q = 0; q < 16; q++) {
            int slot = tid + q * 256;          // 0..4095
            int idx = slot & 2047;             // within-matrix slot
            int r = idx >> 4;                  // 0..127
            int c8 = (idx & 15) * 8;           // 0..120 halves
            if (slot < 2048) {
                if (tileM + r < M)
                    CP16(sS + (uint32_t)(r * FR_ + c8) * 2,
                         A + (size_t)(tileM + r) * 128 + c8);
            } else {
                if (tileN + r < N)
                    CP16(sS + FBUF_ + (uint32_t)(r * FR_ + c8) * 2,
                         B + (size_t)(tileN + r) * 128 + c8);
            }
        }
        CP_COMMIT();
        CP_WAIT0();
        __syncthreads();

        #pragma unroll
        for (int ks = 0; ks < 8; ks++) {
            uint32_t a[4][4];
            #pragma unroll
            for (int mi = 0; mi < 4; mi++) {
                int row = wm + mi * 16 + rr + ((gg & 1) << 3);
                int col = ks * 16 + ((gg >> 1) << 3);
                ldsm_x4(a[mi][0], a[mi][1], a[mi][2], a[mi][3],
                        sS + (uint32_t)(row * FR_ + col) * 2);
            }
            uint32_t b[2][4];
            #pragma unroll
            for (int p = 0; p < 2; p++) {
                int row = wn + p * 16 + rr + ((gg & 1) << 3);
                int col = ks * 16 + ((gg >> 1) << 3);
                ldsm_x4(b[p][0], b[p][1], b[p][2], b[p][3],
                        sS + FBUF_ + (uint32_t)(row * FR_ + col) * 2);
            }
            #pragma unroll
            for (int mi = 0; mi < 4; mi++) {
                #pragma unroll
                for (int nj = 0; nj < 4; nj++) {
                    int p = nj >> 1;
                    uint32_t bb[2];
                    if (nj & 1) { bb[0] = b[p][1]; bb[1] = b[p][3]; }
                    else        { bb[0] = b[p][0]; bb[1] = b[p][2]; }
                    mma16816(acc[mi][nj], a[mi], bb);
                }
            }
        }
    } else {
        // ---- K=512: 3-stage pipeline, chunk 64 ----
        constexpr int KC = K >> 6;
        auto issue = [&](int kc, int stg) {
            int kb = kc * 64;
            #pragma unroll
            for (int q = 0; q < 4; q++) {
                int slot = tid + q * 256;
                int r = slot >> 3, c8 = (slot & 7) * 8;
                uint32_t da = sS + stg * STG_ + (uint32_t)(r * KR_ + c8) * 2;
                if (tileM + r < M) CP16(da, A + (size_t)(tileM + r) * K + kb + c8);
                uint32_t db = sS + 3 * STG_ + stg * STG_ + (uint32_t)(r * KR_ + c8) * 2;
                if (tileN + r < N) CP16(db, B + (size_t)(tileN + r) * K + kb + c8);
            }
        };
        issue(0, 0); CP_COMMIT();
        if (KC > 1) issue(1, 1);
        CP_COMMIT();

        #pragma unroll
        for (int kc = 0; kc < KC; kc++) {
            CP_WAIT1();
            __syncthreads();
            int pc = kc + 2;
            if (pc < KC) issue(pc, pc % 3);
            CP_COMMIT();

            const int stg = kc % 3;
            const uint32_t aBase = sS + stg * STG_;
            const uint32_t bBase = sS + 3 * STG_ + stg * STG_;
            #pragma unroll
            for (int ks = 0; ks < 4; ks++) {
                uint32_t a[4][4];
                #pragma unroll
                for (int mi = 0; mi < 4; mi++) {
                    int row = wm + mi * 16 + rr + ((gg & 1) << 3);
                    int col = ks * 16 + ((gg >> 1) << 3);
                    ldsm_x4(a[mi][0], a[mi][1], a[mi][2], a[mi][3],
                            aBase + (uint32_t)(row * KR_ + col) * 2);
                }
                uint32_t b[2][4];
                #pragma unroll
                for (int p = 0; p < 2; p++) {
                    int row = wn + p * 16 + rr + ((gg & 1) << 3);
                    int col = ks * 16 + ((gg >> 1) << 3);
                    ldsm_x4(b[p][0], b[p][1], b[p][2], b[p][3],
                            bBase + (uint32_t)(row * KR_ + col) * 2);
                }
                #pragma unroll
                for (int mi = 0; mi < 4; mi++) {
                    #pragma unroll
                    for (int nj = 0; nj < 4; nj++) {
                        int p = nj >> 1;
                        uint32_t bb[2];
                        if (nj & 1) { bb[0] = b[p][1]; bb[1] = b[p][3]; }
                        else        { bb[0] = b[p][0]; bb[1] = b[p][2]; }
                        mma16816(acc[mi][nj], a[mi], bb);
                    }
                }
            }
        }
    }

    const int er = lane >> 2, ec = (lane & 3) * 2;
    #pragma unroll
    for (int mi = 0; mi < 4; mi++) {
        #pragma unroll
        for (int half = 0; half < 2; half++) {
            int gm = tileM + wm + mi * 16 + er + half * 8;
            if (gm >= M) continue;
            #pragma unroll
            for (int nj = 0; nj < 4; nj++) {
                int gn = tileN + wn + nj * 8 + ec;
                float vx = acc[mi][nj][half * 2 + 0];
                float vy = acc[mi][nj][half * 2 + 1];
                if (bias) { vx += bias[gn]; vy += bias[gn + 1]; }
                if (EPI == 2) { vx = gelu_exact(vx); vy = gelu_exact(vy); }
                if (EPI == 1 || EPI == 2) {
                    *(__half2*)(Ch + (size_t)gm * N + gn) = __floats2half2_rn(vx, vy);
                } else if (EPI == 3) {
                    int w = gm / WT_, i = gm - w * WT_;
                    int n = w / (NWH_ * NWW_); int rem = w - n * (NWH_ * NWW_);
                    int wh = rem / NWW_, ww = rem - wh * NWW_;
                    int hp = wh * WS_ + i / WS_;
                    int wp = ww * WS_ + i - (i / WS_) * WS_;
                    if (hp < H_ && wp < W_) {
                        size_t o = ((size_t)n * HW + hp * W_ + wp) * C_ + gn;
                        float2 old = *(float2*)(Cf + o);
                        *(float2*)(Cf + o) = make_float2(old.x + vx, old.y + vy);
                    }
                } else if (EPI == 4) {
                    size_t o = (size_t)gm * N + gn;
                    float2 old = *(float2*)(Cf + o);
                    *(float2*)(Cf + o) = make_float2(old.x + vx, old.y + vy);
                } else {
                    size_t o = (size_t)gm * N + gn;
                    *(float2*)(Cf + o) = make_float2(vx, vy);
                    if (EPI == 5)
                        *(__half2*)(Ch + o) = __floats2half2_rn(vx, vy);
                }
            }
        }
    }
}

// ---------------- all weights fp32 -> fp16, one kernel ----------------
__global__ void cvt_weights(const float* __restrict__ cw, const float* __restrict__ qw,
                            const float* __restrict__ pw, const float* __restrict__ f1,
                            const float* __restrict__ f2, __half* __restrict__ wh) {
    int i = blockIdx.x * blockDim.x + threadIdx.x;
    const float* s; int off;
    if (i < WH_QKV)      { s = cw; off = 0; }
    else if (i < WH_PROJ){ s = qw; off = WH_QKV; }
    else if (i < WH_FC1) { s = pw; off = WH_PROJ; }
    else if (i < WH_FC2) { s = f1; off = WH_FC1; }
    else if (i < WH_TOT) { s = f2; off = WH_FC2; }
    else return;
    wh[i] = __float2half(s[i - off]);
}

// ---------------- transpose (n,c,p) -> (n,p,c), fp32 -> half ----------------
__global__ void transpose_ncp(const float* __restrict__ in, __half* __restrict__ out) {
    __shared__ float tile[32][33];
    int n = blockIdx.z;
    int p0 = blockIdx.x * 32, c0 = blockIdx.y * 32;
    int x = threadIdx.x, y = threadIdx.y;
    const float* src = in + (size_t)n * C_ * HW;
    #pragma unroll
    for (int yy = y; yy < 32; yy += 8)
        tile[yy][x] = src[(size_t)(c0 + yy) * HW + p0 + x];
    __syncthreads();
    __half* dst = out + (size_t)n * HW * C_;
    #pragma unroll
    for (int yy = y; yy < 32; yy += 8)
        dst[(size_t)(p0 + yy) * C_ + c0 + x] = __float2half(tile[x][yy]);
}

// ---------------- LN over C=128 into padded window layout, half out (vectorized) ----------------
__global__ void ln_window(const float* __restrict__ tokens,
                          const float* __restrict__ g, const float* __restrict__ b,
                          __half* __restrict__ out) {
    int warp = (blockIdx.x * blockDim.x + threadIdx.x) >> 5;
    int lane = threadIdx.x & 31;
    if (warp >= TOKW_) return;
    int w = warp / WT_, i = warp % WT_;
    int n = w / (NWH_ * NWW_); int rem = w % (NWH_ * NWW_);
    int wh = rem / NWW_, ww = rem % NWW_;
    int hp = wh * WS_ + i / WS_;
    int wp = ww * WS_ + i % WS_;
    __half* orow = out + (size_t)warp * C_;
    if (hp < H_ && wp < W_) {
        const float* irow = tokens + ((size_t)n * HW + hp * W_ + wp) * C_;
        float4 v = *(const float4*)(irow + 4 * lane);
        float mu = warp_sum(v.x + v.y + v.z + v.w) * (1.f / C_);
        float d0 = v.x - mu, d1 = v.y - mu, d2 = v.z - mu, d3 = v.w - mu;
        float var = warp_sum(d0 * d0 + d1 * d1 + d2 * d2 + d3 * d3) * (1.f / C_);
        float rstd = rsqrtf(var + 1e-5f);
        float4 gw = *(const float4*)(g + 4 * lane);
        float4 bw = *(const float4*)(b + 4 * lane);
        __half2 h0 = __floats2half2_rn(d0 * rstd * gw.x + bw.x, d1 * rstd * gw.y + bw.y);
        __half2 h1 = __floats2half2_rn(d2 * rstd * gw.z + bw.z, d3 * rstd * gw.w + bw.w);
        uint2 pk;
        pk.x = *(uint32_t*)&h0; pk.y = *(uint32_t*)&h1;
        *(uint2*)(orow + 4 * lane) = pk;
    } else {
        *(uint2*)(orow + 4 * lane) = make_uint2(0u, 0u);
    }
}

// ---------------- plain LN over rows, half out (vectorized) ----------------
__global__ void ln_rows(const float* __restrict__ in,
                        const float* __restrict__ g, const float* __restrict__ b,
                        __half* __restrict__ out, int rows) {
    int warp = (blockIdx.x * blockDim.x + threadIdx.x) >> 5;
    int lane = threadIdx.x & 31;
    if (warp >= rows) return;
    const float* irow = in + (size_t)warp * C_;
    float4 v = *(const float4*)(irow + 4 * lane);
    float mu = warp_sum(v.x + v.y + v.z + v.w) * (1.f / C_);
    float d0 = v.x - mu, d1 = v.y - mu, d2 = v.z - mu, d3 = v.w - mu;
    float var = warp_sum(d0 * d0 + d1 * d1 + d2 * d2 + d3 * d3) * (1.f / C_);
    float rstd = rsqrtf(var + 1e-5f);
    float4 gw = *(const float4*)(g + 4 * lane);
    float4 bw = *(const float4*)(b + 4 * lane);
    __half2 h0 = __floats2half2_rn(d0 * rstd * gw.x + bw.x, d1 * rstd * gw.y + bw.y);
    __half2 h1 = __floats2half2_rn(d2 * rstd * gw.z + bw.z, d3 * rstd * gw.w + bw.w);
    __half* orow = out + (size_t)warp * C_;
    uint2 pk;
    pk.x = *(uint32_t*)&h0; pk.y = *(uint32_t*)&h1;
    *(uint2*)(orow + 4 * lane) = pk;
}

// ================= attention: tensor cores, one warp per head, P overlays Q/K =================
#define AP_QKV(t, h) ((h)*7680 + (t)*2560)
#define AP_P(h)      ((h)*7680)
#define ATTN_SMEM    (30720 * 2)   // 61440 bytes

__global__ __launch_bounds__(128)
void attn_win(const __half* __restrict__ qkv, __half* __restrict__ out) {
    extern __shared__ __align__(16) __half ash[];
    const int w = blockIdx.x;
    const int tid = threadIdx.x;
    const int wid = tid >> 5, lane = tid & 31;
    const int rr = lane & 7, gg = lane >> 3;
    const int q2 = (lane & 3) * 2;
    const uint32_t sb = smem_u32(ash);

    const __half* src = qkv + (size_t)w * WT_ * 384;
    for (int idx = tid; idx < WT_ * 48; idx += 128) {
        int r = idx / 48, u = idx % 48;
        int t = u >> 4, h = (u >> 2) & 3, seg = u & 3;
        uint32_t dst = sb + (uint32_t)((AP_QKV(t, h) + r * 40 + seg * 8)) * 2;
        CP16(dst, src + (size_t)r * 384 + u * 8);
    }
    CP_COMMIT();
    uint4 z = make_uint4(0u, 0u, 0u, 0u);
    for (int idx = tid; idx < 900; idx += 128) {
        int plane = idx / 75, rem = idx % 75;
        int r = 49 + rem / 5, seg = rem % 5;
        *(uint4*)((char*)ash + (size_t)(plane * 2560 + r * 40 + seg * 8) * 2) = z;
    }
    CP_WAIT0();
    __syncthreads();

    const int h = wid;
    const uint32_t sQ = sb + (uint32_t)AP_QKV(0, h) * 2;
    const uint32_t sK = sb + (uint32_t)AP_QKV(1, h) * 2;
    const uint32_t sV = sb + (uint32_t)AP_QKV(2, h) * 2;
    const uint32_t sP = sb + (uint32_t)AP_P(h) * 2;
    __half* Pp = ash + AP_P(h);

    float s[4][7][4];
    #pragma unroll
    for (int i = 0; i < 4; i++)
        #pragma unroll
        for (int j = 0; j < 7; j++)
            #pragma unroll
            for (int k = 0; k < 4; k++) s[i][j][k] = 0.f;

    #pragma unroll
    for (int ks = 0; ks < 2; ks++) {
        uint32_t a[4][4];
        #pragma unroll
        for (int mi = 0; mi < 4; mi++)
            ldsm_x4(a[mi][0], a[mi][1], a[mi][2], a[mi][3],
                    sQ + (uint32_t)((mi * 16 + rr + ((gg & 1) << 3)) * 40
                                    + ks * 16 + ((gg >> 1) << 3)) * 2);
        uint32_t b[4][4];
        #pragma unroll
        for (int p = 0; p < 4; p++)
            ldsm_x4(b[p][0], b[p][1], b[p][2], b[p][3],
                    sK + (uint32_t)((p * 16 + rr + ((gg & 1) << 3)) * 40
                                    + ks * 16 + ((gg >> 1) << 3)) * 2);
        #pragma unroll
        for (int mi = 0; mi < 4; mi++)
            #pragma unroll
            for (int nj = 0; nj < 7; nj++) {
                int pg = nj >> 1;
                uint32_t bb[2];
                if (nj & 1) { bb[0] = b[pg][1]; bb[1] = b[pg][3]; }
                else        { bb[0] = b[pg][0]; bb[1] = b[pg][2]; }
                mma16816(s[mi][nj], a[mi], bb);
            }
    }
    __syncwarp();

    const float scale = 0.17677669529663687f;
    #pragma unroll
    for (int mi = 0; mi < 4; mi++) {
        #pragma unroll
        for (int hf = 0; hf < 2; hf++) {
            float mx = -1e30f;
            #pragma unroll
            for (int nj = 0; nj < 7; nj++) {
                int c0 = 8 * nj + q2;
                float v0 = s[mi][nj][hf * 2 + 0];
                float v1 = s[mi][nj][hf * 2 + 1];
                if (c0 < WT_) mx = fmaxf(mx, v0);
                if (c0 + 1 < WT_) mx = fmaxf(mx, v1);
            }
            mx = fmaxf(mx, __shfl_xor_sync(0xffffffffu, mx, 1));
            mx = fmaxf(mx, __shfl_xor_sync(0xffffffffu, mx, 2));
            float p0[7], p1[7], sum = 0.f;
            #pragma unroll
            for (int nj = 0; nj < 7; nj++) {
                int c0 = 8 * nj + q2;
                float v0 = s[mi][nj][hf * 2 + 0];
                float v1 = s[mi][nj][hf * 2 + 1];
                p0[nj] = (c0 < WT_)     ? __expf((v0 - mx) * scale) : 0.f;
                p1[nj] = (c0 + 1 < WT_) ? __expf((v1 - mx) * scale) : 0.f;
                sum += p0[nj] + p1[nj];
            }
            sum += __shfl_xor_sync(0xffffffffu, sum, 1);
            sum += __shfl_xor_sync(0xffffffffu, sum, 2);
            float inv = 1.f / sum;
            int row = mi * 16 + (lane >> 2) + hf * 8;
            #pragma unroll
            for (int nj = 0; nj < 7; nj++)
                *(__half2*)(Pp + row * 72 + 8 * nj + q2) =
                    __floats2half2_rn(p0[nj] * inv, p1[nj] * inv);
        }
    }
    for (int r = lane; r < 64; r += 32)
        *(uint4*)(Pp + r * 72 + 56) = make_uint4(0u, 0u, 0u, 0u);
    __syncwarp();

    float o[4][4][4];
    #pragma unroll
    for (int i = 0; i < 4; i++)
        #pragma unroll
        for (int j = 0; j < 4; j++)
            #pragma unroll
            for (int k = 0; k < 4; k++) o[i][j][k] = 0.f;

    #pragma unroll
    for (int ks = 0; ks < 4; ks++) {
        uint32_t a[4][4];
        #pragma unroll
        for (int mi = 0; mi < 4; mi++)
            ldsm_x4(a[mi][0], a[mi][1], a[mi][2], a[mi][3],
                    sP + (uint32_t)((mi * 16 + rr + ((gg & 1) << 3)) * 72
                                    + ks * 16 + ((gg >> 1) << 3)) * 2);
        uint32_t b[2][4];
        #pragma unroll
        for (int g = 0; g < 2; g++) {
            int row = ks * 16 + rr + ((gg >> 1) << 3);
            int col = g * 16 + ((gg & 1) << 3);
            ldsm_x4t(b[g][0], b[g][1], b[g][2], b[g][3],
                     sV + (uint32_t)(row * 40 + col) * 2);
        }
        #pragma unroll
        for (int mi = 0; mi < 4; mi++)
            #pragma unroll
            for (int nd = 0; nd < 4; nd++) {
                int g = nd >> 1;
                uint32_t bb[2];
                if (nd & 1) { bb[0] = b[g][1]; bb[1] = b[g][3]; }
                else        { bb[0] = b[g][0]; bb[1] = b[g][2]; }
                mma16816(o[mi][nd], a[mi], bb);
            }
    }

    #pragma unroll
    for (int mi = 0; mi < 4; mi++) {
        #pragma unroll
        for (int hf = 0; hf < 2; hf++) {
            int row = mi * 16 + (lane >> 2) + hf * 8;
            if (row < WT_) {
                #pragma unroll
                for (int nd = 0; nd < 4; nd++)
                    *(__half2*)(out + ((size_t)(w * WT_ + row)) * C_ + h * HD_ + 8 * nd + q2) =
                        __floats2half2_rn(o[mi][nd][hf * 2], o[mi][nd][hf * 2 + 1]);
            }
        }
    }
}

// ---------------- head mean reduce + tiny MLP ----------------
__global__ void zero_head() { if (threadIdx.x < N_ * C_) g_head[threadIdx.x] = 0.f; }

__global__ void head_reduce(const float* __restrict__ tokens) {
    int n = blockIdx.x / (HW / 128);
    int pb = (blockIdx.x % (HW / 128)) * 128;
    int c = threadIdx.x;
    float s = 0.f;
    for (int i = 0; i < 128; i++) s += tokens[((size_t)n * HW + pb + i) * C_ + c];
    atomicAdd(&g_head[n * C_ + c], s);
}

__global__ void head_mlp(const float* __restrict__ r1w, const float* __restrict__ r1b,
                         const float* __restrict__ r2w, const float* __restrict__ r2b,
                         const float* __restrict__ r3w, const float* __restrict__ r3b,
                         float* __restrict__ out) {
    __shared__ float hh[N_ * C_];
    __shared__ float y1[N_ * 256];
    __shared__ float y2[N_ * 256];
    __shared__ float y3[N_ * DOUT_];
    __shared__ float ssum[N_];
    int tid = threadIdx.x;
    if (tid < N_ * C_) hh[tid] = g_head[tid] * (1.f / HW);
    __syncthreads();
    for (int o = tid; o < N_ * 256; o += 256) {
        int n = o >> 8, j = o & 255;
        float s = r1b[j];
        for (int c = 0; c < C_; c++) s = fmaf(hh[n * C_ + c], r1w[j * C_ + c], s);
        y1[o] = s > 0.f ? s : 0.01f * s;
    }
    __syncthreads();
    for (int o = tid; o < N_ * 256; o += 256) {
        int n = o >> 8, j = o & 255;
        float s = r2b[j];
        for (int c = 0; c < 256; c++) s = fmaf(y1[n * 256 + c], r2w[j * 256 + c], s);
        y2[o] = s > 0.f ? s : 0.01f * s;
    }
    __syncthreads();
    for (int o = tid; o < N_ * DOUT_; o += 256) {
        int n = o >> 8, j = o & 255;
        float s = r3b[j];
        for (int c = 0; c < 256; c++) s = fmaf(y2[n * 256 + c], r3w[j * 256 + c], s);
        y3[o] = fmaxf(s, 0.f) + 0.1f;
    }
    __syncthreads();
    if (tid < N_) {
        float s = 0.f;
        for (int j = 0; j < DOUT_; j++) s += y3[tid * DOUT_ + j];
        ssum[tid] = s;
    }
    __syncthreads();
    for (int o = tid; o < N_ * DOUT_; o += 256) {
        int n = o >> 8;
        out[o] = y3[o] / ssum[n];
    }
}

// ---------------- queries fp32 -> half ----------------
__global__ void cvt_queries(const float* __restrict__ tokens, __half* __restrict__ qh) {
    int i = blockIdx.x * blockDim.x + threadIdx.x;
    if (i < N_ * NQ_ * C_) {
        int n = i / (NQ_ * C_);
        int r = i - n * (NQ_ * C_);
        qh[i] = __float2half(tokens[(size_t)n * HW * C_ + r]);
    }
}

// ---------------- host launch ----------------
static void* symaddr(const void* sym) {
    void* p = nullptr;
    cudaGetSymbolAddress(&p, sym);
    return p;
}

extern "C" void kernel_launch(void* const* d_in, const int* in_sizes, int n_in,
                              void* d_out, int out_size) {
    const float* x      = (const float*)d_in[0];
    const float* conv_w = (const float*)d_in[1];
    const float* conv_b = (const float*)d_in[2];
    const float* n1_g   = (const float*)d_in[3];
    const float* n1_b   = (const float*)d_in[4];
    const float* qkv_w  = (const float*)d_in[5];
    const float* qkv_b  = (const float*)d_in[6];
    const float* proj_w = (const float*)d_in[7];
    const float* proj_b = (const float*)d_in[8];
    const float* n2_g   = (const float*)d_in[9];
    const float* n2_b   = (const float*)d_in[10];
    const float* fc1_w  = (const float*)d_in[11];
    const float* fc1_b  = (const float*)d_in[12];
    const float* fc2_w  = (const float*)d_in[13];
    const float* fc2_b  = (const float*)d_in[14];
    const float* r1_w   = (const float*)d_in[15];
    const float* r1_b   = (const float*)d_in[16];
    const float* r2_w   = (const float*)d_in[17];
    const float* r2_b   = (const float*)d_in[18];
    const float* r3_w   = (const float*)d_in[19];
    const float* r3_b   = (const float*)d_in[20];
    float* out = (float*)d_out;

    __half* xth    = (__half*)symaddr(g_xth);
    __half* tok0h  = (__half*)symaddr(g_tok0h);
    float*  tokens = (float*)symaddr(g_tokens);
    __half* hh     = (__half*)symaddr(g_hh);
    __half* qkvh   = (__half*)symaddr(g_qkvh);
    __half* attnoh = (__half*)symaddr(g_attnoh);
    __half* mlp1h  = (__half*)symaddr(g_mlp1h);
    __half* wh     = (__half*)symaddr(g_wh);
    __half* qh     = (__half*)symaddr(g_qh);

    cudaFuncSetAttribute((const void*)gemm_mma<0,128,1,1>, cudaFuncAttributeMaxDynamicSharedMemorySize, GEMM_SMEM1);
    cudaFuncSetAttribute((const void*)gemm_mma<1,128,1,0>, cudaFuncAttributeMaxDynamicSharedMemorySize, GEMM_SMEM1);
    cudaFuncSetAttribute((const void*)gemm_mma<2,128,1,0>, cudaFuncAttributeMaxDynamicSharedMemorySize, GEMM_SMEM1);
    cudaFuncSetAttribute((const void*)gemm_mma<3,128,1,0>, cudaFuncAttributeMaxDynamicSharedMemorySize, GEMM_SMEM1);
    cudaFuncSetAttribute((const void*)gemm_mma<4,512,3,0>, cudaFuncAttributeMaxDynamicSharedMemorySize, GEMM_SMEM3);
    cudaFuncSetAttribute((const void*)gemm_mma<5,128,1,0>, cudaFuncAttributeMaxDynamicSharedMemorySize, GEMM_SMEM1);
    cudaFuncSetAttribute((const void*)attn_win, cudaFuncAttributeMaxDynamicSharedMemorySize, ATTN_SMEM);

    cvt_weights<<<(WH_TOT + 255) / 256, 256>>>(conv_w, qkv_w, proj_w, fc1_w, fc2_w, wh);

    transpose_ncp<<<dim3(HW / 32, C_ / 32, N_), dim3(32, 8)>>>(x, xth);

    gemm_mma<5,128,1,0><<<dim3(1, (N_ * HW) / 128), 256, GEMM_SMEM1>>>(
        xth, wh + WH_CONV, conv_b, tokens, tok0h, N_ * HW, C_);

    const int mTiles_w = (TOKW_ + 127) / 128;
    const int lnw_blocks = (TOKW_ + 7) / 8;
    const int lnr_blocks = (N_ * HW + 7) / 8;

    for (int d = 0; d < DEPTH_; d++) {
        ln_window<<<lnw_blocks, 256>>>(tokens, n1_g + d * C_, n1_b + d * C_, hh);
        gemm_mma<1,128,1,0><<<dim3(3, mTiles_w), 256, GEMM_SMEM1>>>(
            hh, wh + WH_QKV + (size_t)d * 3 * C_ * C_, qkv_b + d * 3 * C_,
            nullptr, qkvh, TOKW_, 3 * C_);
        attn_win<<<NWIN_, 128, ATTN_SMEM>>>(qkvh, attnoh);
        gemm_mma<3,128,1,0><<<dim3(1, mTiles_w), 256, GEMM_SMEM1>>>(
            attnoh, wh + WH_PROJ + (size_t)d * C_ * C_, proj_b + d * C_,
            tokens, nullptr, TOKW_, C_);
        ln_rows<<<lnr_blocks, 256>>>(tokens, n2_g + d * C_, n2_b + d * C_, hh, N_ * HW);
        gemm_mma<2,128,1,0><<<dim3(HID_ / 128, (N_ * HW) / 128), 256, GEMM_SMEM1>>>(
            hh, wh + WH_FC1 + (size_t)d * HID_ * C_, fc1_b + d * HID_,
            nullptr, mlp1h, N_ * HW, HID_);
        gemm_mma<4,512,3,0><<<dim3(1, (N_ * HW) / 128), 256, GEMM_SMEM3>>>(
            mlp1h, wh + WH_FC2 + (size_t)d * C_ * HID_, fc2_b + d * C_,
            tokens, nullptr, N_ * HW, C_);
    }

    zero_head<<<1, 256>>>();
    head_reduce<<<N_ * (HW / 128), 128>>>(tokens);
    head_mlp<<<1, 256>>>(r1_w, r1_b, r2_w, r2_b, r3_w, r3_b, out);

    cvt_queries<<<(N_ * NQ_ * C_ + 255) / 256, 256>>>(tokens, qh);
    gemm_mma<0,128,1,1><<<dim3(HW / 128, 1, N_), 256, GEMM_SMEM1>>>(
        qh, tok0h, nullptr, out + 512, nullptr, NQ_, HW);
}